// round 15
// baseline (speedup 1.0000x reference)
#include <cuda_runtime.h>
#include <cstdint>

// Persistent col-major DCN CrossLayer: R14 fold-reduce base + register
// double-buffer prefetch. Loads for tile m+1 issue BEFORE the fold/barrier
// of tile m, so DRAM requests stay in flight across the whole
// reduce+barrier+combine+store window.

#define F_DIM 1024
#define NVEC  256
#define THREADS 256
#define NWARPS 8
#define TILE_R 4
#define CTAS_PER_SM 3
#define NSM 148

__device__ __forceinline__ float dot4(float4 a, float4 b, float acc) {
    return fmaf(a.x, b.x, fmaf(a.y, b.y, fmaf(a.z, b.z, fmaf(a.w, b.w, acc))));
}

__global__ __launch_bounds__(THREADS, CTAS_PER_SM)
void cross_fold_pf_kernel(const float* __restrict__ x,
                          const float* __restrict__ kernels,
                          const float* __restrict__ bias,
                          float* __restrict__ out,
                          int ntiles)
{
    __shared__ float red[2][12][NWARPS];

    const int t   = threadIdx.x;        // float4 column 0..255
    const int wid = t >> 5;
    const int lid = t & 31;

    // ---- Prologue: per-column weights into registers ----
    const float4* __restrict__ k4 = reinterpret_cast<const float4*>(kernels);
    const float4* __restrict__ b4 = reinterpret_cast<const float4*>(bias);
    const float4 w0 = __ldg(&k4[t]);
    const float4 w1 = __ldg(&k4[NVEC + t]);
    const float4 w2 = __ldg(&k4[2 * NVEC + t]);
    const float4 b0 = __ldg(&b4[t]);
    const float4 b1 = __ldg(&b4[NVEC + t]);
    const float4 b2 = __ldg(&b4[2 * NVEC + t]);
    float4 bs;
    bs.x = b0.x + b1.x + b2.x;
    bs.y = b0.y + b1.y + b2.y;
    bs.z = b0.z + b1.z + b2.z;
    bs.w = b0.w + b1.w + b2.w;

    // cross constants: c01 = b0.w1, c012 = (b0+b1).w2
    float c01, c012;
    {
        float pc01 = dot4(b0, w1, 0.f);
        float4 b01;
        b01.x = b0.x + b1.x; b01.y = b0.y + b1.y;
        b01.z = b0.z + b1.z; b01.w = b0.w + b1.w;
        float pc012 = dot4(b01, w2, 0.f);
        #pragma unroll
        for (int off = 16; off; off >>= 1) {
            pc01  += __shfl_xor_sync(0xFFFFFFFFu, pc01,  off);
            pc012 += __shfl_xor_sync(0xFFFFFFFFu, pc012, off);
        }
        if (lid == 0) { red[0][0][wid] = pc01; red[0][1][wid] = pc012; }
        __syncthreads();
        float a = 0.f, b = 0.f;
        #pragma unroll
        for (int i = 0; i < NWARPS; i++) { a += red[0][0][i]; b += red[0][1][i]; }
        c01 = a; c012 = b;
        __syncthreads();     // protect red[0] before the main loop reuses it
    }

    const float4* __restrict__ x4 = reinterpret_cast<const float4*>(x);
    float4* __restrict__ o4       = reinterpret_cast<float4*>(out);

    // Fold-reduce lane bookkeeping (constant per thread).
    const int b4i = (lid >> 4) & 1;
    const int b3i = (lid >> 3) & 1;
    const int b2i = (lid >> 2) & 1;
    const int b1i = (lid >> 1) & 1;
    const int b0i = lid & 1;
    const int myidx  = 6 * b4i + 3 * b3i + (b1i ? 2 : b2i);
    const bool writer = (b0i == 0) && (b1i ? (b2i == 0) : true);

    const int tile0 = blockIdx.x;
    const int gstep = gridDim.x;

    // ---- Pipeline prologue: load first tile into xc ----
    float4 xc[TILE_R];
    if (tile0 < ntiles) {
        const size_t base0 = (size_t)tile0 * TILE_R * NVEC + t;
        #pragma unroll
        for (int r = 0; r < TILE_R; r++)
            xc[r] = __ldcs(&x4[base0 + (size_t)r * NVEC]);
    }

    int it = 0;
    #pragma unroll 1
    for (int tile = tile0; tile < ntiles; tile += gstep, ++it) {
        const size_t base = (size_t)tile * TILE_R * NVEC + t;

        // ---- Dots from current tile (consume xc early) ----
        float p[12];
        #pragma unroll
        for (int r = 0; r < TILE_R; r++) {
            p[r]     = dot4(xc[r], w0, 0.f);
            p[4 + r] = dot4(xc[r], w1, 0.f);
            p[8 + r] = dot4(xc[r], w2, 0.f);
        }

        // ---- Prefetch next tile (in flight across fold+barrier+store) ----
        float4 xn[TILE_R];
        {
            long ntile = (long)tile + gstep;
            const size_t nb = (ntile < ntiles ? (size_t)ntile : (size_t)tile)
                              * TILE_R * NVEC + t;
            #pragma unroll
            for (int r = 0; r < TILE_R; r++)
                xn[r] = __ldcs(&x4[nb + (size_t)r * NVEC]);
        }

        // ---- Fold reduction: 12 values -> 1 per lane (13 SHFL) ----
        float f6[6];
        {
            const bool hi = b4i;
            #pragma unroll
            for (int j = 0; j < 6; j++) {
                const float send = hi ? p[j] : p[j + 6];
                const float recv = __shfl_xor_sync(0xFFFFFFFFu, send, 16);
                f6[j] = (hi ? p[j + 6] : p[j]) + recv;
            }
        }
        float f3[3];
        {
            const bool hi = b3i;
            #pragma unroll
            for (int j = 0; j < 3; j++) {
                const float send = hi ? f6[j] : f6[j + 3];
                const float recv = __shfl_xor_sync(0xFFFFFFFFu, send, 8);
                f3[j] = (hi ? f6[j + 3] : f6[j]) + recv;
            }
        }
        float z01, z2;
        {
            const bool hi = b2i;
            const float send = hi ? f3[0] : f3[1];
            const float recv = __shfl_xor_sync(0xFFFFFFFFu, send, 4);
            z01 = (hi ? f3[1] : f3[0]) + recv;
            z2  = f3[2] + __shfl_xor_sync(0xFFFFFFFFu, f3[2], 4);
        }
        float zz;
        {
            const bool hi = b1i;
            const float send = hi ? z01 : z2;
            const float recv = __shfl_xor_sync(0xFFFFFFFFu, send, 2);
            zz = (hi ? z2 : z01) + recv;
        }
        zz += __shfl_xor_sync(0xFFFFFFFFu, zz, 1);

        const int buf = it & 1;
        if (writer) red[buf][myidx][wid] = zz;
        __syncthreads();                 // the only barrier per tile

        // ---- All-warp redundant combine ----
        float val = 0.f;
        if (lid < 12) {
            #pragma unroll
            for (int w = 0; w < NWARPS; w++) val += red[buf][lid][w];
        }

        // ---- Alphas + stores (xc still in registers) ----
        #pragma unroll
        for (int r = 0; r < TILE_R; r++) {
            const float d0 = __shfl_sync(0xFFFFFFFFu, val, r);
            const float d1 = __shfl_sync(0xFFFFFFFFu, val, 4 + r);
            const float d2 = __shfl_sync(0xFFFFFFFFu, val, 8 + r);
            const float t1 = 1.f + d0;
            const float s1 = fmaf(t1, d1, c01);
            const float t2 = t1 + s1;
            const float s2 = fmaf(t2, d2, c012);
            const float a  = t2 + s2;
            float4 o;
            o.x = fmaf(a, xc[r].x, bs.x);
            o.y = fmaf(a, xc[r].y, bs.y);
            o.z = fmaf(a, xc[r].z, bs.z);
            o.w = fmaf(a, xc[r].w, bs.w);
            __stcs(&o4[base + (size_t)r * NVEC], o);
        }

        // ---- Rotate ----
        #pragma unroll
        for (int r = 0; r < TILE_R; r++) xc[r] = xn[r];
    }
}

extern "C" void kernel_launch(void* const* d_in, const int* in_sizes, int n_in,
                              void* d_out, int out_size)
{
    const float* x       = (const float*)d_in[0];
    const float* kernels = (const float*)d_in[1];
    const float* bias    = (const float*)d_in[2];
    float* out           = (float*)d_out;

    const int B = in_sizes[0] / F_DIM;              // 16384
    const int ntiles = (B + TILE_R - 1) / TILE_R;   // 4096
    int grid = NSM * 4;                             // 592: even tile split
    if (grid > ntiles) grid = ntiles;

    cross_fold_pf_kernel<<<grid, THREADS>>>(x, kernels, bias, out, ntiles);
}

// round 16
// speedup vs baseline: 1.2490x; 1.2490x over previous
#include <cuda_runtime.h>
#include <cstdint>

// Persistent col-major DCN CrossLayer: R14 fold-reduce base + SMEM-STASH
// prefetch. Per tile: dots consume xc -> STS xc to thread-private stash ->
// LDG next tile into the SAME xc registers (overlaps fold+barrier+store) ->
// fold -> one barrier -> combine -> store reads the stash.
// Stash is thread-private (same thread writes then reads) — no extra sync.

#define F_DIM 1024
#define NVEC  256
#define THREADS 256
#define NWARPS 8
#define TILE_R 4
#define CTAS_PER_SM 4
#define NSM 148

__device__ __forceinline__ float dot4(float4 a, float4 b, float acc) {
    return fmaf(a.x, b.x, fmaf(a.y, b.y, fmaf(a.z, b.z, fmaf(a.w, b.w, acc))));
}

__global__ __launch_bounds__(THREADS, CTAS_PER_SM)
void cross_stash_kernel(const float* __restrict__ x,
                        const float* __restrict__ kernels,
                        const float* __restrict__ bias,
                        float* __restrict__ out,
                        int ntiles)
{
    __shared__ float4 stash[TILE_R * NVEC];       // 16 KB thread-private stash
    __shared__ float  red[2][12][NWARPS];

    const int t   = threadIdx.x;        // float4 column 0..255
    const int wid = t >> 5;
    const int lid = t & 31;

    // ---- Prologue: per-column weights into registers ----
    const float4* __restrict__ k4 = reinterpret_cast<const float4*>(kernels);
    const float4* __restrict__ b4 = reinterpret_cast<const float4*>(bias);
    const float4 w0 = __ldg(&k4[t]);
    const float4 w1 = __ldg(&k4[NVEC + t]);
    const float4 w2 = __ldg(&k4[2 * NVEC + t]);
    const float4 b0 = __ldg(&b4[t]);
    const float4 b1 = __ldg(&b4[NVEC + t]);
    const float4 b2 = __ldg(&b4[2 * NVEC + t]);
    float4 bs;
    bs.x = b0.x + b1.x + b2.x;
    bs.y = b0.y + b1.y + b2.y;
    bs.z = b0.z + b1.z + b2.z;
    bs.w = b0.w + b1.w + b2.w;

    // cross constants: c01 = b0.w1, c012 = (b0+b1).w2
    float c01, c012;
    {
        float pc01 = dot4(b0, w1, 0.f);
        float4 b01;
        b01.x = b0.x + b1.x; b01.y = b0.y + b1.y;
        b01.z = b0.z + b1.z; b01.w = b0.w + b1.w;
        float pc012 = dot4(b01, w2, 0.f);
        #pragma unroll
        for (int off = 16; off; off >>= 1) {
            pc01  += __shfl_xor_sync(0xFFFFFFFFu, pc01,  off);
            pc012 += __shfl_xor_sync(0xFFFFFFFFu, pc012, off);
        }
        if (lid == 0) { red[0][0][wid] = pc01; red[0][1][wid] = pc012; }
        __syncthreads();
        float a = 0.f, b = 0.f;
        #pragma unroll
        for (int i = 0; i < NWARPS; i++) { a += red[0][0][i]; b += red[0][1][i]; }
        c01 = a; c012 = b;
        __syncthreads();     // protect red[0] before the main loop reuses it
    }

    const float4* __restrict__ x4 = reinterpret_cast<const float4*>(x);
    float4* __restrict__ o4       = reinterpret_cast<float4*>(out);

    // Fold-reduce lane bookkeeping (constant per thread).
    const int b4i = (lid >> 4) & 1;
    const int b3i = (lid >> 3) & 1;
    const int b2i = (lid >> 2) & 1;
    const int b1i = (lid >> 1) & 1;
    const int b0i = lid & 1;
    const int myidx  = 6 * b4i + 3 * b3i + (b1i ? 2 : b2i);
    const bool writer = (b0i == 0) && (b1i ? (b2i == 0) : true);

    const int tile0 = blockIdx.x;
    const int gstep = gridDim.x;

    // ---- Pipeline prologue: load first tile into xc ----
    float4 xc[TILE_R];
    if (tile0 < ntiles) {
        const size_t base0 = (size_t)tile0 * TILE_R * NVEC + t;
        #pragma unroll
        for (int r = 0; r < TILE_R; r++)
            xc[r] = __ldcs(&x4[base0 + (size_t)r * NVEC]);
    }

    int it = 0;
    #pragma unroll 1
    for (int tile = tile0; tile < ntiles; tile += gstep, ++it) {
        const size_t base = (size_t)tile * TILE_R * NVEC + t;

        // ---- Dots from current tile ----
        float p[12];
        #pragma unroll
        for (int r = 0; r < TILE_R; r++) {
            p[r]     = dot4(xc[r], w0, 0.f);
            p[4 + r] = dot4(xc[r], w1, 0.f);
            p[8 + r] = dot4(xc[r], w2, 0.f);
        }

        // ---- Stash xc to smem, then REUSE xc regs for the next tile ----
        #pragma unroll
        for (int r = 0; r < TILE_R; r++)
            stash[r * NVEC + t] = xc[r];
        {
            long nt = (long)tile + gstep;
            const size_t nb = (nt < ntiles ? (size_t)nt : (size_t)tile)
                              * TILE_R * NVEC + t;
            #pragma unroll
            for (int r = 0; r < TILE_R; r++)
                xc[r] = __ldcs(&x4[nb + (size_t)r * NVEC]);   // in flight below
        }

        // ---- Fold reduction: 12 values -> 1 per lane (13 SHFL) ----
        float f6[6];
        {
            const bool hi = b4i;
            #pragma unroll
            for (int j = 0; j < 6; j++) {
                const float send = hi ? p[j] : p[j + 6];
                const float recv = __shfl_xor_sync(0xFFFFFFFFu, send, 16);
                f6[j] = (hi ? p[j + 6] : p[j]) + recv;
            }
        }
        float f3[3];
        {
            const bool hi = b3i;
            #pragma unroll
            for (int j = 0; j < 3; j++) {
                const float send = hi ? f6[j] : f6[j + 3];
                const float recv = __shfl_xor_sync(0xFFFFFFFFu, send, 8);
                f3[j] = (hi ? f6[j + 3] : f6[j]) + recv;
            }
        }
        float z01, z2;
        {
            const bool hi = b2i;
            const float send = hi ? f3[0] : f3[1];
            const float recv = __shfl_xor_sync(0xFFFFFFFFu, send, 4);
            z01 = (hi ? f3[1] : f3[0]) + recv;
            z2  = f3[2] + __shfl_xor_sync(0xFFFFFFFFu, f3[2], 4);
        }
        float zz;
        {
            const bool hi = b1i;
            const float send = hi ? z01 : z2;
            const float recv = __shfl_xor_sync(0xFFFFFFFFu, send, 2);
            zz = (hi ? z2 : z01) + recv;
        }
        zz += __shfl_xor_sync(0xFFFFFFFFu, zz, 1);

        const int buf = it & 1;
        if (writer) red[buf][myidx][wid] = zz;
        __syncthreads();                 // the only barrier per tile

        // ---- All-warp redundant combine ----
        float val = 0.f;
        if (lid < 12) {
            #pragma unroll
            for (int w = 0; w < NWARPS; w++) val += red[buf][lid][w];
        }

        // ---- Alphas + stores (x read back from the stash) ----
        #pragma unroll
        for (int r = 0; r < TILE_R; r++) {
            const float d0 = __shfl_sync(0xFFFFFFFFu, val, r);
            const float d1 = __shfl_sync(0xFFFFFFFFu, val, 4 + r);
            const float d2 = __shfl_sync(0xFFFFFFFFu, val, 8 + r);
            const float t1 = 1.f + d0;
            const float s1 = fmaf(t1, d1, c01);
            const float t2 = t1 + s1;
            const float s2 = fmaf(t2, d2, c012);
            const float a  = t2 + s2;
            const float4 xv = stash[r * NVEC + t];
            float4 o;
            o.x = fmaf(a, xv.x, bs.x);
            o.y = fmaf(a, xv.y, bs.y);
            o.z = fmaf(a, xv.z, bs.z);
            o.w = fmaf(a, xv.w, bs.w);
            __stcs(&o4[base + (size_t)r * NVEC], o);
        }
    }
}

extern "C" void kernel_launch(void* const* d_in, const int* in_sizes, int n_in,
                              void* d_out, int out_size)
{
    const float* x       = (const float*)d_in[0];
    const float* kernels = (const float*)d_in[1];
    const float* bias    = (const float*)d_in[2];
    float* out           = (float*)d_out;

    const int B = in_sizes[0] / F_DIM;              // 16384
    const int ntiles = (B + TILE_R - 1) / TILE_R;   // 4096
    int grid = NSM * CTAS_PER_SM;                   // 592
    if (grid > ntiles) grid = ntiles;

    cross_stash_kernel<<<grid, THREADS>>>(x, kernels, bias, out, ntiles);
}